// round 15
// baseline (speedup 1.0000x reference)
#include <cuda_runtime.h>
#include <math_constants.h>

#define NB 4096
#define NC 1000
#define NT 9

#define LOG2E  1.4426950408889634f
#define LN2    0.6931471805599453f
#define C20K   0.07213475204444817f   /* 0.05 * log2(e) */
#define CTHR   0.7213475204444817f    /* 0.5  * log2(e) */

__device__ float    g_A[NB];   // CE
__device__ float    g_B[NB];   // (sum_t e_t * tgl_t * (KD_t - CE)) / sum_t e_t
__device__ float    g_R[NB];   // max over 8 teachers
__device__ unsigned g_cnt;     // completion ticket (reset by last CTA)

__device__ __forceinline__ float ex2f(float x) {
    float r; asm("ex2.approx.ftz.f32 %0, %1;" : "=f"(r) : "f"(x)); return r;
}
__device__ __forceinline__ float lg2f(float x) {
    float r; asm("lg2.approx.ftz.f32 %0, %1;" : "=f"(r) : "f"(x)); return r;
}

#define PROC_T(q, t) { \
    const float vv0 = (q).x, vv1 = (q).y, vv2 = (q).z, vv3 = (q).w; \
    msum[0] += vv0; msum[1] += vv1; msum[2] += vv2; msum[3] += vv3; \
    float e; \
    e = ex2f(vv0 * C20K); Z[t] += e; A[t] = fmaf(e, sv[0], A[t]); m[t] = fmaxf(m[t], vv0 + msk[0]); \
    e = ex2f(vv1 * C20K); Z[t] += e; A[t] = fmaf(e, sv[1], A[t]); m[t] = fmaxf(m[t], vv1 + msk[1]); \
    e = ex2f(vv2 * C20K); Z[t] += e; A[t] = fmaf(e, sv[2], A[t]); m[t] = fmaxf(m[t], vv2 + msk[2]); \
    e = ex2f(vv3 * C20K); Z[t] += e; A[t] = fmaf(e, sv[3], A[t]); m[t] = fmaxf(m[t], vv3 + msk[3]); \
}

__global__ __launch_bounds__(256, 4)
void mt_rows_kernel(const float* __restrict__ p0, const float* __restrict__ p1,
                    const float* __restrict__ p2, const float* __restrict__ p3,
                    const float* __restrict__ p4, const float* __restrict__ p5,
                    const float* __restrict__ p6, const float* __restrict__ p7,
                    const float* __restrict__ ps, const int* __restrict__ ptgt,
                    float* __restrict__ dout)
{
    const int b    = blockIdx.x;
    const int tid  = threadIdx.x;
    const int lane = tid & 31;
    const int wid  = tid >> 5;

    // int64-declared targets materialize as int32 under JAX x64-off; probe layout.
    const bool is64 = (ptgt[1] == 0) & (ptgt[3] == 0) & (ptgt[5] == 0) & (ptgt[7] == 0);
    const int tgt = is64 ? ptgt[2 * b] : ptgt[b];

    const size_t row = (size_t)b * NC;

    __shared__ float sm[8][4][30];   // [warp][lane-class][var], stride 30: conflict-free
    __shared__ unsigned s_last;

    float m[NT], Z[NT], A[NT];
#pragma unroll
    for (int t = 0; t < NT; t++) { m[t] = -CUDART_INF_F; Z[t] = 0.f; A[t] = 0.f; }
    float zs1 = 0.f, zs20 = 0.f;

    if (tid < 250) {
        const int c0 = tid * 4;

        // group 1: student + teachers 0..3 (MLP = 5)
        const float4 sq = *(const float4*)(ps + row + c0);
        const float4 q0 = *(const float4*)(p0 + row + c0);
        const float4 q1 = *(const float4*)(p1 + row + c0);
        const float4 q2 = *(const float4*)(p2 + row + c0);
        const float4 q3 = *(const float4*)(p3 + row + c0);

        const float sv[4] = {sq.x, sq.y, sq.z, sq.w};
        float msk[4];
#pragma unroll
        for (int j = 0; j < 4; j++) {
            msk[j] = ((c0 + j) == tgt) ? -CUDART_INF_F : 0.f;
            zs1  += ex2f(sv[j] * LOG2E);
            zs20 += ex2f(sv[j] * C20K);
        }

        float msum[4] = {0.f, 0.f, 0.f, 0.f};
        PROC_T(q0, 0) PROC_T(q1, 1) PROC_T(q2, 2) PROC_T(q3, 3)

        // group 2: teachers 4..7
        const float4 q4 = *(const float4*)(p4 + row + c0);
        const float4 q5 = *(const float4*)(p5 + row + c0);
        const float4 q6 = *(const float4*)(p6 + row + c0);
        const float4 q7 = *(const float4*)(p7 + row + c0);
        PROC_T(q4, 4) PROC_T(q5, 5) PROC_T(q6, 6) PROC_T(q7, 7)

        // mimic (t = 8)
#pragma unroll
        for (int j = 0; j < 4; j++) {
            const float mim = msum[j] * 0.125f;
            const float e = ex2f(mim * C20K);
            Z[8] += e;
            A[8] = fmaf(e, sv[j], A[8]);
            m[8] = fmaxf(m[8], mim + msk[j]);
        }
    }

    // 3-level xor tree -> lanes 0..3 hold partials for their mod-4 class
#pragma unroll
    for (int off = 16; off >= 4; off >>= 1) {
#pragma unroll
        for (int t = 0; t < NT; t++) {
            m[t] = fmaxf(m[t], __shfl_xor_sync(0xffffffffu, m[t], off));
            Z[t] += __shfl_xor_sync(0xffffffffu, Z[t], off);
            A[t] += __shfl_xor_sync(0xffffffffu, A[t], off);
        }
        zs1  += __shfl_xor_sync(0xffffffffu, zs1, off);
        zs20 += __shfl_xor_sync(0xffffffffu, zs20, off);
    }
    if (lane < 4) {
#pragma unroll
        for (int t = 0; t < NT; t++) {
            sm[wid][lane][t]      = m[t];
            sm[wid][lane][9 + t]  = Z[t];
            sm[wid][lane][18 + t] = A[t];
        }
        sm[wid][lane][27] = zs1;
        sm[wid][lane][28] = zs20;
    }
    __syncthreads();

    if (wid == 0) {
        // lane L reduces variable L over 32 partial-sets (vars 0..8 max, 9..28 sum)
        const int vL = (lane < 29) ? lane : 0;
        float acc = (lane < 9) ? -CUDART_INF_F : 0.f;
#pragma unroll
        for (int i = 0; i < 32; i++) {
            const float x = sm[i >> 2][i & 3][vL];
            acc = (lane < 9) ? fmaxf(acc, x) : (acc + x);
        }
        const int t = (lane < NT) ? lane : 0;
        const float gm   = __shfl_sync(0xffffffffu, acc, t);
        const float gZ   = __shfl_sync(0xffffffffu, acc, 9 + t);
        const float gA   = __shfl_sync(0xffffffffu, acc, 18 + t);
        const float gz1  = __shfl_sync(0xffffffffu, acc, 27);
        const float gz20 = __shfl_sync(0xffffffffu, acc, 28);

        // target logits re-loaded directly (L1/L2-hot)
        const float stg = __ldg(ps + row + tgt);
        const float* tp = (lane < 4)
            ? ((lane < 2) ? (lane == 0 ? p0 : p1) : (lane == 2 ? p2 : p3))
            : ((lane < 6) ? (lane == 4 ? p4 : p5) : (lane == 6 ? p6 : p7));
        float tgl = (lane < 8) ? __ldg(tp + row + tgt) : 0.f;
        float ts = tgl;
#pragma unroll
        for (int off = 4; off; off >>= 1)
            ts += __shfl_xor_sync(0xffffffffu, ts, off);
        const float mimtg = __shfl_sync(0xffffffffu, ts, 0) * 0.125f;
        if (lane == 8) tgl = mimtg;

        const float CE    = lg2f(gz1) * LN2 - stg;
        const float lse20 = lg2f(gz20) * LN2;

        float e = 0.f, contrib = 0.f, rmaxv = -CUDART_INF_F;
        if (lane < NT) {
            const float kd = 400.f * lse20 - 20.f * (gA / gZ);
            const float margin = fmaxf(0.f, tgl - gm);
            e = ex2f(margin * CTHR);
            contrib = e * tgl * (kd - CE);
            if (lane < 8) rmaxv = fmaxf(gm, tgl);
        }
        float se = e, nm = contrib, rm = rmaxv;
#pragma unroll
        for (int off = 8; off; off >>= 1) {
            se += __shfl_xor_sync(0xffffffffu, se, off);
            nm += __shfl_xor_sync(0xffffffffu, nm, off);
            rm = fmaxf(rm, __shfl_xor_sync(0xffffffffu, rm, off));
        }
        if (lane == 0) {
            g_A[b] = CE;
            g_B[b] = nm / se;
            g_R[b] = rm;
            __threadfence();
            s_last = (atomicAdd(&g_cnt, 1u) == NB - 1) ? 1u : 0u;
        }
    }
    __syncthreads();

    // ---- last CTA: deterministic final reduce over L2-resident partials ----
    if (s_last) {
        float a = 0.f, bsum = 0.f, r = -CUDART_INF_F;
#pragma unroll 4
        for (int k = 0; k < NB / 256; k++) {
            const int i = tid + k * 256;
            a    += g_A[i];
            bsum += g_B[i];
            r = fmaxf(r, g_R[i]);
        }
#pragma unroll
        for (int off = 16; off; off >>= 1) {
            a    += __shfl_xor_sync(0xffffffffu, a, off);
            bsum += __shfl_xor_sync(0xffffffffu, bsum, off);
            r = fmaxf(r, __shfl_xor_sync(0xffffffffu, r, off));
        }
        // reuse sm[][][] as a tiny cross-warp buffer (safe: after syncthreads)
        if (lane == 0) {
            sm[wid][0][0] = a;
            sm[wid][0][1] = bsum;
            sm[wid][0][2] = r;
        }
        __syncthreads();
        if (tid == 0) {
            float ta = 0.f, tb = 0.f, tr = -CUDART_INF_F;
#pragma unroll
            for (int w = 0; w < 8; w++) {
                ta += sm[w][0][0];
                tb += sm[w][0][1];
                tr = fmaxf(tr, sm[w][0][2]);
            }
            dout[0] = ta * (1.f / NB) + 0.8f * tb / (tr * NB);
            __threadfence();
            atomicExch(&g_cnt, 0u);   // reset for next graph replay
        }
    }
}

extern "C" void kernel_launch(void* const* d_in, const int* in_sizes, int n_in,
                              void* d_out, int out_size)
{
    (void)in_sizes; (void)n_in; (void)out_size;
    mt_rows_kernel<<<NB, 256>>>(
        (const float*)d_in[0], (const float*)d_in[1],
        (const float*)d_in[2], (const float*)d_in[3],
        (const float*)d_in[4], (const float*)d_in[5],
        (const float*)d_in[6], (const float*)d_in[7],
        (const float*)d_in[8], (const int*)d_in[9],
        (float*)d_out);
}

// round 16
// speedup vs baseline: 1.0734x; 1.0734x over previous
#include <cuda_runtime.h>
#include <math_constants.h>

#define NB 4096
#define NC 1000
#define NT 9
#define GRID 592              /* 148 SMs x 4 CTAs — persistent */

#define LOG2E  1.4426950408889634f
#define LN2    0.6931471805599453f
#define C20K   0.07213475204444817f   /* 0.05 * log2(e) */
#define CTHR   0.7213475204444817f    /* 0.5  * log2(e) */

__device__ float g_A[NB];   // CE
__device__ float g_B[NB];   // (sum_t e_t * tgl_t * (KD_t - CE)) / sum_t e_t
__device__ float g_R[NB];   // max over 8 teachers

__device__ __forceinline__ float ex2f(float x) {
    float r; asm("ex2.approx.ftz.f32 %0, %1;" : "=f"(r) : "f"(x)); return r;
}
__device__ __forceinline__ float lg2f(float x) {
    float r; asm("lg2.approx.ftz.f32 %0, %1;" : "=f"(r) : "f"(x)); return r;
}

#define PROC_T(q, t) { \
    const float vv0 = (q).x, vv1 = (q).y, vv2 = (q).z, vv3 = (q).w; \
    msum[0] += vv0; msum[1] += vv1; msum[2] += vv2; msum[3] += vv3; \
    float e; \
    e = ex2f(vv0 * C20K); Z[t] += e; A[t] = fmaf(e, sv[0], A[t]); m[t] = fmaxf(m[t], vv0 + msk[0]); \
    e = ex2f(vv1 * C20K); Z[t] += e; A[t] = fmaf(e, sv[1], A[t]); m[t] = fmaxf(m[t], vv1 + msk[1]); \
    e = ex2f(vv2 * C20K); Z[t] += e; A[t] = fmaf(e, sv[2], A[t]); m[t] = fmaxf(m[t], vv2 + msk[2]); \
    e = ex2f(vv3 * C20K); Z[t] += e; A[t] = fmaf(e, sv[3], A[t]); m[t] = fmaxf(m[t], vv3 + msk[3]); \
}

__global__ __launch_bounds__(256, 4)
void mt_rows_kernel(const float* __restrict__ p0, const float* __restrict__ p1,
                    const float* __restrict__ p2, const float* __restrict__ p3,
                    const float* __restrict__ p4, const float* __restrict__ p5,
                    const float* __restrict__ p6, const float* __restrict__ p7,
                    const float* __restrict__ ps, const int* __restrict__ ptgt)
{
    const int tid  = threadIdx.x;
    const int lane = tid & 31;
    const int wid  = tid >> 5;
    const bool valid = (tid < 250);
    const int c0 = tid * 4;

    // int64-declared targets materialize as int32 under JAX x64-off; probe once.
    const bool is64 = (ptgt[1] == 0) & (ptgt[3] == 0) & (ptgt[5] == 0) & (ptgt[7] == 0);

    __shared__ float sm[8][4][30];   // [warp][lane-class][var], stride 30: conflict-free

    int b = blockIdx.x;

    // software-pipeline prologue: first sample's student + T0 + T1
    float4 sq, q0, q1;
    if (valid) {
        const size_t r0 = (size_t)b * NC;
        sq = *(const float4*)(ps + r0 + c0);
        q0 = *(const float4*)(p0 + r0 + c0);
        q1 = *(const float4*)(p1 + r0 + c0);
    }

    for (;;) {
        const size_t row = (size_t)b * NC;
        const int tgt = is64 ? ptgt[2 * b] : ptgt[b];

        float m[NT], Z[NT], A[NT];
#pragma unroll
        for (int t = 0; t < NT; t++) { m[t] = -CUDART_INF_F; Z[t] = 0.f; A[t] = 0.f; }
        float zs1 = 0.f, zs20 = 0.f;

        if (valid) {
            // complete group 1 (q2,q3 join the in-flight sq,q0,q1)
            const float4 q2 = *(const float4*)(p2 + row + c0);
            const float4 q3 = *(const float4*)(p3 + row + c0);

            const float sv[4] = {sq.x, sq.y, sq.z, sq.w};
            float msk[4];
#pragma unroll
            for (int j = 0; j < 4; j++) {
                msk[j] = ((c0 + j) == tgt) ? -CUDART_INF_F : 0.f;
                zs1  += ex2f(sv[j] * LOG2E);
                zs20 += ex2f(sv[j] * C20K);
            }

            float msum[4] = {0.f, 0.f, 0.f, 0.f};
            PROC_T(q0, 0) PROC_T(q1, 1) PROC_T(q2, 2) PROC_T(q3, 3)

            // group 2: teachers 4..7
            const float4 q4 = *(const float4*)(p4 + row + c0);
            const float4 q5 = *(const float4*)(p5 + row + c0);
            const float4 q6 = *(const float4*)(p6 + row + c0);
            const float4 q7 = *(const float4*)(p7 + row + c0);
            PROC_T(q4, 4) PROC_T(q5, 5) PROC_T(q6, 6) PROC_T(q7, 7)

            // mimic (t = 8)
#pragma unroll
            for (int j = 0; j < 4; j++) {
                const float mim = msum[j] * 0.125f;
                const float e = ex2f(mim * C20K);
                Z[8] += e;
                A[8] = fmaf(e, sv[j], A[8]);
                m[8] = fmaxf(m[8], mim + msk[j]);
            }
        }

        // prefetch NEXT sample's student + T0 + T1 before the compute-only phase
        const int bn = b + GRID;
        const bool more = (bn < NB);
        if (more && valid) {
            const size_t rn = (size_t)bn * NC;
            sq = *(const float4*)(ps + rn + c0);
            q0 = *(const float4*)(p0 + rn + c0);
            q1 = *(const float4*)(p1 + rn + c0);
        }

        // 3-level xor tree -> lanes 0..3 hold partials for their mod-4 class
#pragma unroll
        for (int off = 16; off >= 4; off >>= 1) {
#pragma unroll
            for (int t = 0; t < NT; t++) {
                m[t] = fmaxf(m[t], __shfl_xor_sync(0xffffffffu, m[t], off));
                Z[t] += __shfl_xor_sync(0xffffffffu, Z[t], off);
                A[t] += __shfl_xor_sync(0xffffffffu, A[t], off);
            }
            zs1  += __shfl_xor_sync(0xffffffffu, zs1, off);
            zs20 += __shfl_xor_sync(0xffffffffu, zs20, off);
        }
        if (lane < 4) {
#pragma unroll
            for (int t = 0; t < NT; t++) {
                sm[wid][lane][t]      = m[t];
                sm[wid][lane][9 + t]  = Z[t];
                sm[wid][lane][18 + t] = A[t];
            }
            sm[wid][lane][27] = zs1;
            sm[wid][lane][28] = zs20;
        }
        __syncthreads();

        if (wid == 0) {
            // lane L reduces variable L over 32 partial-sets (vars 0..8 max, 9..28 sum)
            const int vL = (lane < 29) ? lane : 0;
            float acc = (lane < 9) ? -CUDART_INF_F : 0.f;
#pragma unroll
            for (int i = 0; i < 32; i++) {
                const float x = sm[i >> 2][i & 3][vL];
                acc = (lane < 9) ? fmaxf(acc, x) : (acc + x);
            }
            const int t = (lane < NT) ? lane : 0;
            const float gm   = __shfl_sync(0xffffffffu, acc, t);
            const float gZ   = __shfl_sync(0xffffffffu, acc, 9 + t);
            const float gA   = __shfl_sync(0xffffffffu, acc, 18 + t);
            const float gz1  = __shfl_sync(0xffffffffu, acc, 27);
            const float gz20 = __shfl_sync(0xffffffffu, acc, 28);

            // target logits re-loaded directly (L1/L2-hot)
            const float stg = __ldg(ps + row + tgt);
            const float* tp = (lane < 4)
                ? ((lane < 2) ? (lane == 0 ? p0 : p1) : (lane == 2 ? p2 : p3))
                : ((lane < 6) ? (lane == 4 ? p4 : p5) : (lane == 6 ? p6 : p7));
            float tgl = (lane < 8) ? __ldg(tp + row + tgt) : 0.f;
            float ts = tgl;
#pragma unroll
            for (int off = 4; off; off >>= 1)
                ts += __shfl_xor_sync(0xffffffffu, ts, off);
            const float mimtg = __shfl_sync(0xffffffffu, ts, 0) * 0.125f;
            if (lane == 8) tgl = mimtg;

            const float CE    = lg2f(gz1) * LN2 - stg;
            const float lse20 = lg2f(gz20) * LN2;

            float e = 0.f, contrib = 0.f, rmaxv = -CUDART_INF_F;
            if (lane < NT) {
                const float kd = 400.f * lse20 - 20.f * (gA / gZ);
                const float margin = fmaxf(0.f, tgl - gm);
                e = ex2f(margin * CTHR);
                contrib = e * tgl * (kd - CE);
                if (lane < 8) rmaxv = fmaxf(gm, tgl);
            }
            float se = e, nm = contrib, rm = rmaxv;
#pragma unroll
            for (int off = 8; off; off >>= 1) {
                se += __shfl_xor_sync(0xffffffffu, se, off);
                nm += __shfl_xor_sync(0xffffffffu, nm, off);
                rm = fmaxf(rm, __shfl_xor_sync(0xffffffffu, rm, off));
            }
            if (lane == 0) {
                g_A[b] = CE;
                g_B[b] = nm / se;
                g_R[b] = rm;
            }
        }

        if (!more) break;
        b = bn;
        __syncthreads();   // smem reuse guard before next iteration's writes
    }
}

__global__ __launch_bounds__(1024)
void mt_final_kernel(float* __restrict__ dout)
{
    const int tid  = threadIdx.x;
    const int lane = tid & 31;
    const int wid  = tid >> 5;
    __shared__ float sA[32], sB[32], sR[32];

    const float4 a4 = *(const float4*)(g_A + tid * 4);
    const float4 b4 = *(const float4*)(g_B + tid * 4);
    const float4 r4 = *(const float4*)(g_R + tid * 4);
    float a  = (a4.x + a4.y) + (a4.z + a4.w);
    float bb = (b4.x + b4.y) + (b4.z + b4.w);
    float r  = fmaxf(fmaxf(r4.x, r4.y), fmaxf(r4.z, r4.w));
#pragma unroll
    for (int off = 16; off; off >>= 1) {
        a  += __shfl_xor_sync(0xffffffffu, a, off);
        bb += __shfl_xor_sync(0xffffffffu, bb, off);
        r = fmaxf(r, __shfl_xor_sync(0xffffffffu, r, off));
    }
    if (lane == 0) { sA[wid] = a; sB[wid] = bb; sR[wid] = r; }
    __syncthreads();
    if (tid == 0) {
        float ta = 0.f, tb = 0.f, tr = -CUDART_INF_F;
#pragma unroll
        for (int w = 0; w < 32; w++) {
            ta += sA[w]; tb += sB[w]; tr = fmaxf(tr, sR[w]);
        }
        dout[0] = ta * (1.f / NB) + 0.8f * tb / (tr * NB);
    }
}

extern "C" void kernel_launch(void* const* d_in, const int* in_sizes, int n_in,
                              void* d_out, int out_size)
{
    (void)in_sizes; (void)n_in; (void)out_size;
    mt_rows_kernel<<<GRID, 256>>>(
        (const float*)d_in[0], (const float*)d_in[1],
        (const float*)d_in[2], (const float*)d_in[3],
        (const float*)d_in[4], (const float*)d_in[5],
        (const float*)d_in[6], (const float*)d_in[7],
        (const float*)d_in[8], (const int*)d_in[9]);
    mt_final_kernel<<<1, 1024>>>((float*)d_out);
}

// round 17
// speedup vs baseline: 1.1785x; 1.0979x over previous
#include <cuda_runtime.h>
#include <math_constants.h>

#define NB 4096
#define NC 1000
#define NT 9

#define LOG2E  1.4426950408889634f
#define LN2    0.6931471805599453f
#define C20K   0.07213475204444817f   /* 0.05 * log2(e) */
#define CTHR   0.7213475204444817f    /* 0.5  * log2(e) */

__device__ float g_A[NB];   // CE
__device__ float g_B[NB];   // (sum_t e_t * tgl_t * (KD_t - CE)) / sum_t e_t
__device__ float g_R[NB];   // max over 8 teachers

__device__ __forceinline__ float ex2f(float x) {
    float r; asm("ex2.approx.ftz.f32 %0, %1;" : "=f"(r) : "f"(x)); return r;
}
__device__ __forceinline__ float lg2f(float x) {
    float r; asm("lg2.approx.ftz.f32 %0, %1;" : "=f"(r) : "f"(x)); return r;
}

#define PROC_T(q, t) { \
    const float vv0 = (q).x, vv1 = (q).y, vv2 = (q).z, vv3 = (q).w; \
    msum[0] += vv0; msum[1] += vv1; msum[2] += vv2; msum[3] += vv3; \
    float e; \
    e = ex2f(vv0 * C20K); Z[t] += e; A[t] = fmaf(e, sv[0], A[t]); m[t] = fmaxf(m[t], vv0 + msk[0]); \
    e = ex2f(vv1 * C20K); Z[t] += e; A[t] = fmaf(e, sv[1], A[t]); m[t] = fmaxf(m[t], vv1 + msk[1]); \
    e = ex2f(vv2 * C20K); Z[t] += e; A[t] = fmaf(e, sv[2], A[t]); m[t] = fmaxf(m[t], vv2 + msk[2]); \
    e = ex2f(vv3 * C20K); Z[t] += e; A[t] = fmaf(e, sv[3], A[t]); m[t] = fmaxf(m[t], vv3 + msk[3]); \
}

__global__ __launch_bounds__(256, 4)
void mt_rows_kernel(const float* __restrict__ p0, const float* __restrict__ p1,
                    const float* __restrict__ p2, const float* __restrict__ p3,
                    const float* __restrict__ p4, const float* __restrict__ p5,
                    const float* __restrict__ p6, const float* __restrict__ p7,
                    const float* __restrict__ ps, const int* __restrict__ ptgt)
{
    // allow the dependent (final) kernel to begin launching now; it will block
    // at griddepcontrol.wait until this grid fully completes.
    asm volatile("griddepcontrol.launch_dependents;");

    const int b    = blockIdx.x;
    const int tid  = threadIdx.x;
    const int lane = tid & 31;
    const int wid  = tid >> 5;

    // int64-declared targets materialize as int32 under JAX x64-off; probe layout.
    const bool is64 = (ptgt[1] == 0) & (ptgt[3] == 0) & (ptgt[5] == 0) & (ptgt[7] == 0);
    const int tgt = is64 ? ptgt[2 * b] : ptgt[b];

    const size_t row = (size_t)b * NC;

    __shared__ float sm[8][4][30];   // [warp][lane-class][var], stride 30: conflict-free

    float m[NT], Z[NT], A[NT];
#pragma unroll
    for (int t = 0; t < NT; t++) { m[t] = -CUDART_INF_F; Z[t] = 0.f; A[t] = 0.f; }
    float zs1 = 0.f, zs20 = 0.f;

    if (tid < 250) {
        const int c0 = tid * 4;

        // group 1: student + teachers 0..3 (MLP = 5)
        const float4 sq = *(const float4*)(ps + row + c0);
        const float4 q0 = *(const float4*)(p0 + row + c0);
        const float4 q1 = *(const float4*)(p1 + row + c0);
        const float4 q2 = *(const float4*)(p2 + row + c0);
        const float4 q3 = *(const float4*)(p3 + row + c0);

        const float sv[4] = {sq.x, sq.y, sq.z, sq.w};
        float msk[4];
#pragma unroll
        for (int j = 0; j < 4; j++) {
            msk[j] = ((c0 + j) == tgt) ? -CUDART_INF_F : 0.f;
            zs1  += ex2f(sv[j] * LOG2E);
            zs20 += ex2f(sv[j] * C20K);
        }

        float msum[4] = {0.f, 0.f, 0.f, 0.f};
        PROC_T(q0, 0) PROC_T(q1, 1) PROC_T(q2, 2) PROC_T(q3, 3)

        // group 2: teachers 4..7
        const float4 q4 = *(const float4*)(p4 + row + c0);
        const float4 q5 = *(const float4*)(p5 + row + c0);
        const float4 q6 = *(const float4*)(p6 + row + c0);
        const float4 q7 = *(const float4*)(p7 + row + c0);
        PROC_T(q4, 4) PROC_T(q5, 5) PROC_T(q6, 6) PROC_T(q7, 7)

        // mimic (t = 8)
#pragma unroll
        for (int j = 0; j < 4; j++) {
            const float mim = msum[j] * 0.125f;
            const float e = ex2f(mim * C20K);
            Z[8] += e;
            A[8] = fmaf(e, sv[j], A[8]);
            m[8] = fmaxf(m[8], mim + msk[j]);
        }
    }

    // 3-level xor tree -> lanes 0..3 hold partials for their mod-4 class
#pragma unroll
    for (int off = 16; off >= 4; off >>= 1) {
#pragma unroll
        for (int t = 0; t < NT; t++) {
            m[t] = fmaxf(m[t], __shfl_xor_sync(0xffffffffu, m[t], off));
            Z[t] += __shfl_xor_sync(0xffffffffu, Z[t], off);
            A[t] += __shfl_xor_sync(0xffffffffu, A[t], off);
        }
        zs1  += __shfl_xor_sync(0xffffffffu, zs1, off);
        zs20 += __shfl_xor_sync(0xffffffffu, zs20, off);
    }
    if (lane < 4) {
#pragma unroll
        for (int t = 0; t < NT; t++) {
            sm[wid][lane][t]      = m[t];
            sm[wid][lane][9 + t]  = Z[t];
            sm[wid][lane][18 + t] = A[t];
        }
        sm[wid][lane][27] = zs1;
        sm[wid][lane][28] = zs20;
    }
    __syncthreads();

    if (wid == 0) {
        // lane L reduces variable L over 32 partial-sets (vars 0..8 max, 9..28 sum)
        const int vL = (lane < 29) ? lane : 0;
        float acc = (lane < 9) ? -CUDART_INF_F : 0.f;
#pragma unroll
        for (int i = 0; i < 32; i++) {
            const float x = sm[i >> 2][i & 3][vL];
            acc = (lane < 9) ? fmaxf(acc, x) : (acc + x);
        }
        const int t = (lane < NT) ? lane : 0;
        const float gm   = __shfl_sync(0xffffffffu, acc, t);
        const float gZ   = __shfl_sync(0xffffffffu, acc, 9 + t);
        const float gA   = __shfl_sync(0xffffffffu, acc, 18 + t);
        const float gz1  = __shfl_sync(0xffffffffu, acc, 27);
        const float gz20 = __shfl_sync(0xffffffffu, acc, 28);

        // target logits re-loaded directly (L1/L2-hot)
        const float stg = __ldg(ps + row + tgt);
        const float* tp = (lane < 4)
            ? ((lane < 2) ? (lane == 0 ? p0 : p1) : (lane == 2 ? p2 : p3))
            : ((lane < 6) ? (lane == 4 ? p4 : p5) : (lane == 6 ? p6 : p7));
        float tgl = (lane < 8) ? __ldg(tp + row + tgt) : 0.f;
        float ts = tgl;
#pragma unroll
        for (int off = 4; off; off >>= 1)
            ts += __shfl_xor_sync(0xffffffffu, ts, off);
        const float mimtg = __shfl_sync(0xffffffffu, ts, 0) * 0.125f;
        if (lane == 8) tgl = mimtg;

        const float CE    = lg2f(gz1) * LN2 - stg;
        const float lse20 = lg2f(gz20) * LN2;

        float e = 0.f, contrib = 0.f, rmaxv = -CUDART_INF_F;
        if (lane < NT) {
            const float kd = 400.f * lse20 - 20.f * (gA / gZ);
            const float margin = fmaxf(0.f, tgl - gm);
            e = ex2f(margin * CTHR);
            contrib = e * tgl * (kd - CE);
            if (lane < 8) rmaxv = fmaxf(gm, tgl);
        }
        float se = e, nm = contrib, rm = rmaxv;
#pragma unroll
        for (int off = 8; off; off >>= 1) {
            se += __shfl_xor_sync(0xffffffffu, se, off);
            nm += __shfl_xor_sync(0xffffffffu, nm, off);
            rm = fmaxf(rm, __shfl_xor_sync(0xffffffffu, rm, off));
        }
        if (lane == 0) {
            g_A[b] = CE;
            g_B[b] = nm / se;
            g_R[b] = rm;
        }
    }
}

__global__ __launch_bounds__(1024)
void mt_final_kernel(float* __restrict__ dout)
{
    const int tid  = threadIdx.x;
    const int lane = tid & 31;
    const int wid  = tid >> 5;
    __shared__ float sA[32], sB[32], sR[32];

    // PDL: we may have launched while mt_rows_kernel was still running.
    // Block here until it completes and its writes are visible.
    asm volatile("griddepcontrol.wait;" ::: "memory");

    const float4 a4 = *(const float4*)(g_A + tid * 4);
    const float4 b4 = *(const float4*)(g_B + tid * 4);
    const float4 r4 = *(const float4*)(g_R + tid * 4);
    float a  = (a4.x + a4.y) + (a4.z + a4.w);
    float bb = (b4.x + b4.y) + (b4.z + b4.w);
    float r  = fmaxf(fmaxf(r4.x, r4.y), fmaxf(r4.z, r4.w));
#pragma unroll
    for (int off = 16; off; off >>= 1) {
        a  += __shfl_xor_sync(0xffffffffu, a, off);
        bb += __shfl_xor_sync(0xffffffffu, bb, off);
        r = fmaxf(r, __shfl_xor_sync(0xffffffffu, r, off));
    }
    if (lane == 0) { sA[wid] = a; sB[wid] = bb; sR[wid] = r; }
    __syncthreads();
    if (tid == 0) {
        float ta = 0.f, tb = 0.f, tr = -CUDART_INF_F;
#pragma unroll
        for (int w = 0; w < 32; w++) {
            ta += sA[w]; tb += sB[w]; tr = fmaxf(tr, sR[w]);
        }
        dout[0] = ta * (1.f / NB) + 0.8f * tb / (tr * NB);
    }
}

extern "C" void kernel_launch(void* const* d_in, const int* in_sizes, int n_in,
                              void* d_out, int out_size)
{
    (void)in_sizes; (void)n_in; (void)out_size;
    mt_rows_kernel<<<NB, 256>>>(
        (const float*)d_in[0], (const float*)d_in[1],
        (const float*)d_in[2], (const float*)d_in[3],
        (const float*)d_in[4], (const float*)d_in[5],
        (const float*)d_in[6], (const float*)d_in[7],
        (const float*)d_in[8], (const int*)d_in[9]);

    // final kernel with Programmatic Dependent Launch: launches while rows
    // kernel is still executing; griddepcontrol.wait provides the ordering.
    cudaLaunchConfig_t cfg = {};
    cfg.gridDim  = dim3(1, 1, 1);
    cfg.blockDim = dim3(1024, 1, 1);
    cudaLaunchAttribute attrs[1];
    attrs[0].id = cudaLaunchAttributeProgrammaticStreamSerialization;
    attrs[0].val.programmaticStreamSerializationAllowed = 1;
    cfg.attrs = attrs;
    cfg.numAttrs = 1;
    cudaLaunchKernelEx(&cfg, mt_final_kernel, (float*)d_out);
}